// round 12
// baseline (speedup 1.0000x reference)
#include <cuda_runtime.h>
#include <cuda_fp16.h>
#include <cstdint>

#define N_DIM 2048
#define H_DIM 2048
#define V_DIM 32000

// ---- scratch ----
__device__ __half g_Wh[(size_t)V_DIM * H_DIM];   // 131 MB
__device__ __half g_xh[(size_t)N_DIM * H_DIM];   // 8 MB
__device__ double g_acc;
__device__ unsigned g_count = 0;

// ============================================================
// Kernel 1: fp32 -> fp16 conversion; zero accumulator
// ============================================================
__global__ void convert_kernel(const float* __restrict__ x,
                               const float* __restrict__ W) {
    size_t tid = (size_t)blockIdx.x * blockDim.x + threadIdx.x;
    size_t stride = (size_t)gridDim.x * blockDim.x;
    if (tid == 0) g_acc = 0.0;

    const size_t nW4 = (size_t)V_DIM * H_DIM / 4;
    const float4* W4 = (const float4*)W;
    for (size_t i = tid; i < nW4; i += stride) {
        float4 v = W4[i];
        __half2* dst = (__half2*)(g_Wh + i * 4);
        dst[0] = __floats2half2_rn(v.x, v.y);
        dst[1] = __floats2half2_rn(v.z, v.w);
    }
    const size_t nx4 = (size_t)N_DIM * H_DIM / 4;
    const float4* x4 = (const float4*)x;
    for (size_t i = tid; i < nx4; i += stride) {
        float4 v = x4[i];
        __half2* dst = (__half2*)(g_xh + i * 4);
        dst[0] = __floats2half2_rn(v.x, v.y);
        dst[1] = __floats2half2_rn(v.z, v.w);
    }
}

// ============================================================
// Kernel 2: fp16 HMMA GEMM (f16 acc), 2 CTAs/SM
//   CTA tile 128x128, BK=64; 8 warps (4 M x 2 N), warp tile 32x64
//   -> 6 ldmatrix per 16 MMAs (half the smem traffic of 64x32)
//   3-stage cp.async; fused MSE reduce + last-CTA finalize
// ============================================================
#define BM 128
#define BN 128
#define BK 64
#define NK (H_DIM / BK)               // 32
#define STAGES 3
#define A_BYTES (BM * BK * 2)         // 16384
#define B_BYTES (BN * BK * 2)         // 16384
#define STAGE_BYTES (A_BYTES + B_BYTES)    // 32768
#define SMEM_BYTES (STAGES * STAGE_BYTES)  // 98304 -> 2 CTAs = 192KB
#define THREADS 256
#define NUM_CTAS ((N_DIM / BM) * (V_DIM / BN))   // 4000

__device__ __forceinline__ void cp_async16(uint32_t smem_addr, const void* gptr) {
    asm volatile("cp.async.cg.shared.global [%0], [%1], 16;"
                 :: "r"(smem_addr), "l"(gptr));
}

__global__ void __launch_bounds__(THREADS, 2)
gemm_mse_kernel(const float* __restrict__ y, float* __restrict__ out) {
    extern __shared__ __align__(1024) char smem[];
    __shared__ float red[8];

    const int tid = threadIdx.x;
    const int lane = tid & 31;
    const int warp = tid >> 5;
    const int warp_m = warp & 3;   // 0..3 -> 32-row slabs (M)
    const int warp_n = warp >> 2;  // 0..1 -> 64-col slabs (N)

    const uint32_t sbase = (uint32_t)__cvta_generic_to_shared(smem);

    const int n_blk = blockIdx.x * BM;
    const int v_blk = blockIdx.y * BN;
    const __half* gA = g_xh + (size_t)n_blk * H_DIM;
    const __half* gB = g_Wh + (size_t)v_blk * H_DIM;

    // loader: 1024 16B-chunks per matrix (4/thread each)
    auto issue_tile = [&](int kt) {
        const uint32_t st = sbase + (kt % STAGES) * STAGE_BYTES;
        const __half* gAk = gA + kt * BK;
        const __half* gBk = gB + kt * BK;
        #pragma unroll
        for (int i = 0; i < 4; i++) {
            int chunk = i * THREADS + tid;   // 0..1023
            int row = chunk >> 3;            // 0..127
            int c16 = chunk & 7;
            uint32_t off = (uint32_t)(row * 128 + ((c16 ^ (row & 7)) * 16));
            cp_async16(st + off, gAk + (size_t)row * H_DIM + c16 * 8);
            cp_async16(st + A_BYTES + off, gBk + (size_t)row * H_DIM + c16 * 8);
        }
        asm volatile("cp.async.commit_group;");
    };

    issue_tile(0);
    issue_tile(1);

    // f16x2 accumulators: warp tile 32x64 -> 2 mi x 8 ni x 2 regs = 32 regs
    uint32_t c[2][8][2];
    #pragma unroll
    for (int mi = 0; mi < 2; mi++)
        #pragma unroll
        for (int ni = 0; ni < 8; ni++) { c[mi][ni][0] = 0u; c[mi][ni][1] = 0u; }

    // A: rows warp_m*32 + mi*16 + (lane&15), k-chunk lane>>4
    const int a_row_base = warp_m * 32 + (lane & 15);
    const int a_kc_lane = lane >> 4;                  // 0/1
    // B: rows warp_n*64 + p*16 + (lane&7)+((lane>>4)<<3), k-chunk (lane>>3)&1
    const int b_row_base = warp_n * 64 + (lane & 7) + ((lane >> 4) << 3);
    const int b_kc_lane = (lane >> 3) & 1;

    for (int kt = 0; kt < NK; kt++) {
        asm volatile("cp.async.wait_group 1;");
        __syncthreads();

        const uint32_t aBase = sbase + (kt % STAGES) * STAGE_BYTES;
        const uint32_t bBase = aBase + A_BYTES;

        #pragma unroll
        for (int ks = 0; ks < 4; ks++) {   // 4 x k16 per tile
            uint32_t a[2][4];
            #pragma unroll
            for (int mi = 0; mi < 2; mi++) {
                int row = a_row_base + mi * 16;
                int kc = ks * 2 + a_kc_lane;
                uint32_t addr = aBase + (uint32_t)(row * 128 + ((kc ^ (row & 7)) * 16));
                asm volatile(
                    "ldmatrix.sync.aligned.m8n8.x4.shared.b16 {%0,%1,%2,%3}, [%4];"
                    : "=r"(a[mi][0]), "=r"(a[mi][1]), "=r"(a[mi][2]), "=r"(a[mi][3])
                    : "r"(addr));
            }
            uint32_t b[4][4];
            #pragma unroll
            for (int p = 0; p < 4; p++) {
                int row = b_row_base + p * 16;
                int kc = ks * 2 + b_kc_lane;
                uint32_t addr = bBase + (uint32_t)(row * 128 + ((kc ^ (row & 7)) * 16));
                asm volatile(
                    "ldmatrix.sync.aligned.m8n8.x4.shared.b16 {%0,%1,%2,%3}, [%4];"
                    : "=r"(b[p][0]), "=r"(b[p][1]), "=r"(b[p][2]), "=r"(b[p][3])
                    : "r"(addr));
            }
            #pragma unroll
            for (int mi = 0; mi < 2; mi++) {
                #pragma unroll
                for (int ni = 0; ni < 8; ni++) {
                    int p = ni >> 1;
                    int o = (ni & 1) * 2;
                    asm volatile(
                        "mma.sync.aligned.m16n8k16.row.col.f16.f16.f16.f16 "
                        "{%0,%1}, {%2,%3,%4,%5}, {%6,%7}, {%0,%1};"
                        : "+r"(c[mi][ni][0]), "+r"(c[mi][ni][1])
                        : "r"(a[mi][0]), "r"(a[mi][1]), "r"(a[mi][2]), "r"(a[mi][3]),
                          "r"(b[p][o]), "r"(b[p][o + 1]));
                }
            }
        }

        if (kt + 2 < NK) issue_tile(kt + 2);
        else asm volatile("cp.async.commit_group;");
    }

    // ---- epilogue: (logit - y)^2 ----
    const int gr = lane >> 2;
    const int gc = (lane & 3) * 2;
    float acc = 0.0f;
    #pragma unroll
    for (int mi = 0; mi < 2; mi++) {
        int gn0 = n_blk + warp_m * 32 + mi * 16 + gr;
        const float* y0 = y + (size_t)gn0 * V_DIM + v_blk;
        const float* y8 = y0 + (size_t)8 * V_DIM;
        #pragma unroll
        for (int ni = 0; ni < 8; ni++) {
            int col = warp_n * 64 + ni * 8 + gc;
            float2 y01 = *(const float2*)(y0 + col);
            float2 y23 = *(const float2*)(y8 + col);
            float2 c01 = __half22float2(*(__half2*)&c[mi][ni][0]);
            float2 c23 = __half22float2(*(__half2*)&c[mi][ni][1]);
            float d0 = c01.x - y01.x;
            float d1 = c01.y - y01.y;
            float d2 = c23.x - y23.x;
            float d3 = c23.y - y23.y;
            acc += d0 * d0 + d1 * d1 + d2 * d2 + d3 * d3;
        }
    }
    #pragma unroll
    for (int off = 16; off; off >>= 1)
        acc += __shfl_xor_sync(0xFFFFFFFFu, acc, off);
    if (lane == 0) red[warp] = acc;
    __syncthreads();
    if (warp == 0) {
        float sv = (lane < 8) ? red[lane] : 0.0f;
        #pragma unroll
        for (int off = 4; off; off >>= 1)
            sv += __shfl_xor_sync(0xFFFFFFFFu, sv, off);
        if (lane == 0) {
            atomicAdd(&g_acc, (double)sv);
            __threadfence();
            unsigned done = atomicAdd(&g_count, 1u);
            if (done == NUM_CTAS - 1) {
                double total = atomicAdd(&g_acc, 0.0);   // ordered read
                out[0] = (float)(total / ((double)N_DIM * (double)V_DIM));
                g_count = 0;   // reset for next graph replay
            }
        }
    }
}

// ============================================================
extern "C" void kernel_launch(void* const* d_in, const int* in_sizes, int n_in,
                              void* d_out, int out_size) {
    (void)in_sizes; (void)n_in; (void)out_size;
    const float* x = (const float*)d_in[0];   // [N, H]
    const float* y = (const float*)d_in[1];   // [N, V]
    const float* W = (const float*)d_in[2];   // [V, H]
    float* out = (float*)d_out;

    static bool attr_set = false;
    if (!attr_set) {
        cudaFuncSetAttribute(gemm_mse_kernel,
                             cudaFuncAttributeMaxDynamicSharedMemorySize,
                             SMEM_BYTES);
        attr_set = true;
    }

    convert_kernel<<<2048, 256>>>(x, W);

    dim3 grid(N_DIM / BM, V_DIM / BN);  // (16, 250): x-fastest -> W stripe L2 reuse
    gemm_mse_kernel<<<grid, THREADS, SMEM_BYTES>>>(y, out);
}

// round 13
// speedup vs baseline: 1.0551x; 1.0551x over previous
#include <cuda_runtime.h>
#include <cuda_fp16.h>
#include <cstdint>

#define N_DIM 2048
#define H_DIM 2048
#define V_DIM 32000

// ---- scratch ----
__device__ __half g_Wh[(size_t)V_DIM * H_DIM];   // 131 MB
__device__ __half g_xh[(size_t)N_DIM * H_DIM];   // 8 MB
__device__ double g_acc;
__device__ unsigned g_count = 0;

// ============================================================
// Kernel 1: fp32 -> fp16 conversion; zero accumulator
// ============================================================
__global__ void convert_kernel(const float* __restrict__ x,
                               const float* __restrict__ W) {
    size_t tid = (size_t)blockIdx.x * blockDim.x + threadIdx.x;
    size_t stride = (size_t)gridDim.x * blockDim.x;
    if (tid == 0) g_acc = 0.0;

    const size_t nW4 = (size_t)V_DIM * H_DIM / 4;
    const float4* W4 = (const float4*)W;
    for (size_t i = tid; i < nW4; i += stride) {
        float4 v = W4[i];
        __half2* dst = (__half2*)(g_Wh + i * 4);
        dst[0] = __floats2half2_rn(v.x, v.y);
        dst[1] = __floats2half2_rn(v.z, v.w);
    }
    const size_t nx4 = (size_t)N_DIM * H_DIM / 4;
    const float4* x4 = (const float4*)x;
    for (size_t i = tid; i < nx4; i += stride) {
        float4 v = x4[i];
        __half2* dst = (__half2*)(g_xh + i * 4);
        dst[0] = __floats2half2_rn(v.x, v.y);
        dst[1] = __floats2half2_rn(v.z, v.w);
    }
}

// ============================================================
// Kernel 2: fp16 HMMA GEMM (f16 acc), 3 CTAs/SM (6 warps/SMSP)
//   CTA tile 128x128, BK=64; 8 warps (2 M x 4 N), warp tile 64x32
//   2-stage cp.async (64KB smem); fused MSE reduce + last-CTA finalize
// ============================================================
#define BM 128
#define BN 128
#define BK 64
#define NK (H_DIM / BK)               // 32
#define STAGES 2
#define A_BYTES (BM * BK * 2)         // 16384
#define B_BYTES (BN * BK * 2)         // 16384
#define STAGE_BYTES (A_BYTES + B_BYTES)    // 32768
#define SMEM_BYTES (STAGES * STAGE_BYTES)  // 65536 -> 3 CTAs = 192KB
#define THREADS 256
#define NUM_CTAS ((N_DIM / BM) * (V_DIM / BN))   // 4000

__device__ __forceinline__ void cp_async16(uint32_t smem_addr, const void* gptr) {
    asm volatile("cp.async.cg.shared.global [%0], [%1], 16;"
                 :: "r"(smem_addr), "l"(gptr));
}

__global__ void __launch_bounds__(THREADS, 3)
gemm_mse_kernel(const float* __restrict__ y, float* __restrict__ out) {
    extern __shared__ __align__(1024) char smem[];
    __shared__ float red[8];

    const int tid = threadIdx.x;
    const int lane = tid & 31;
    const int warp = tid >> 5;
    const int warp_m = warp & 1;   // 0..1 -> 64-row slabs (M)
    const int warp_n = warp >> 1;  // 0..3 -> 32-col slabs (N)

    const uint32_t sbase = (uint32_t)__cvta_generic_to_shared(smem);

    const int n_blk = blockIdx.x * BM;
    const int v_blk = blockIdx.y * BN;
    const __half* gA = g_xh + (size_t)n_blk * H_DIM;
    const __half* gB = g_Wh + (size_t)v_blk * H_DIM;

    // loader: 1024 16B-chunks per matrix (4/thread each)
    auto issue_tile = [&](int kt) {
        const uint32_t st = sbase + (kt & 1) * STAGE_BYTES;
        const __half* gAk = gA + kt * BK;
        const __half* gBk = gB + kt * BK;
        #pragma unroll
        for (int i = 0; i < 4; i++) {
            int chunk = i * THREADS + tid;   // 0..1023
            int row = chunk >> 3;            // 0..127
            int c16 = chunk & 7;
            uint32_t off = (uint32_t)(row * 128 + ((c16 ^ (row & 7)) * 16));
            cp_async16(st + off, gAk + (size_t)row * H_DIM + c16 * 8);
            cp_async16(st + A_BYTES + off, gBk + (size_t)row * H_DIM + c16 * 8);
        }
        asm volatile("cp.async.commit_group;");
    };

    issue_tile(0);

    // f16x2 accumulators: warp tile 64x32 -> 4 mi x 4 ni x 2 regs = 32 regs
    uint32_t c[4][4][2];
    #pragma unroll
    for (int mi = 0; mi < 4; mi++)
        #pragma unroll
        for (int ni = 0; ni < 4; ni++) { c[mi][ni][0] = 0u; c[mi][ni][1] = 0u; }

    // round-1-validated fragment addressing
    const int a_row_base = warp_m * 64 + (lane & 15);
    const int a_kc_lane = lane >> 4;                  // 0/1
    const int b_row_base = warp_n * 32 + (lane & 7) + ((lane >> 4) << 3);
    const int b_kc_lane = (lane >> 3) & 1;

    for (int kt = 0; kt < NK; kt++) {
        asm volatile("cp.async.wait_group 0;");
        __syncthreads();
        if (kt + 1 < NK) issue_tile(kt + 1);   // overlaps compute of kt

        const uint32_t aBase = sbase + (kt & 1) * STAGE_BYTES;
        const uint32_t bBase = aBase + A_BYTES;

        #pragma unroll
        for (int ks = 0; ks < 4; ks++) {   // 4 x k16 per tile
            uint32_t a[4][4];
            #pragma unroll
            for (int mi = 0; mi < 4; mi++) {
                int row = a_row_base + mi * 16;
                int kc = ks * 2 + a_kc_lane;
                uint32_t addr = aBase + (uint32_t)(row * 128 + ((kc ^ (row & 7)) * 16));
                asm volatile(
                    "ldmatrix.sync.aligned.m8n8.x4.shared.b16 {%0,%1,%2,%3}, [%4];"
                    : "=r"(a[mi][0]), "=r"(a[mi][1]), "=r"(a[mi][2]), "=r"(a[mi][3])
                    : "r"(addr));
            }
            uint32_t b[2][4];
            #pragma unroll
            for (int p = 0; p < 2; p++) {
                int row = b_row_base + p * 16;
                int kc = ks * 2 + b_kc_lane;
                uint32_t addr = bBase + (uint32_t)(row * 128 + ((kc ^ (row & 7)) * 16));
                asm volatile(
                    "ldmatrix.sync.aligned.m8n8.x4.shared.b16 {%0,%1,%2,%3}, [%4];"
                    : "=r"(b[p][0]), "=r"(b[p][1]), "=r"(b[p][2]), "=r"(b[p][3])
                    : "r"(addr));
            }
            #pragma unroll
            for (int mi = 0; mi < 4; mi++) {
                #pragma unroll
                for (int ni = 0; ni < 4; ni++) {
                    int p = ni >> 1;
                    int o = (ni & 1) * 2;
                    asm volatile(
                        "mma.sync.aligned.m16n8k16.row.col.f16.f16.f16.f16 "
                        "{%0,%1}, {%2,%3,%4,%5}, {%6,%7}, {%0,%1};"
                        : "+r"(c[mi][ni][0]), "+r"(c[mi][ni][1])
                        : "r"(a[mi][0]), "r"(a[mi][1]), "r"(a[mi][2]), "r"(a[mi][3]),
                          "r"(b[p][o]), "r"(b[p][o + 1]));
                }
            }
        }
    }

    // ---- epilogue: (logit - y)^2 ----
    const int gr = lane >> 2;
    const int gc = (lane & 3) * 2;
    float acc = 0.0f;
    #pragma unroll
    for (int mi = 0; mi < 4; mi++) {
        int gn0 = n_blk + warp_m * 64 + mi * 16 + gr;
        const float* y0 = y + (size_t)gn0 * V_DIM + v_blk;
        const float* y8 = y0 + (size_t)8 * V_DIM;
        #pragma unroll
        for (int ni = 0; ni < 4; ni++) {
            int col = warp_n * 32 + ni * 8 + gc;
            float2 y01 = *(const float2*)(y0 + col);
            float2 y23 = *(const float2*)(y8 + col);
            float2 c01 = __half22float2(*(__half2*)&c[mi][ni][0]);
            float2 c23 = __half22float2(*(__half2*)&c[mi][ni][1]);
            float d0 = c01.x - y01.x;
            float d1 = c01.y - y01.y;
            float d2 = c23.x - y23.x;
            float d3 = c23.y - y23.y;
            acc += d0 * d0 + d1 * d1 + d2 * d2 + d3 * d3;
        }
    }
    #pragma unroll
    for (int off = 16; off; off >>= 1)
        acc += __shfl_xor_sync(0xFFFFFFFFu, acc, off);
    if (lane == 0) red[warp] = acc;
    __syncthreads();
    if (warp == 0) {
        float sv = (lane < 8) ? red[lane] : 0.0f;
        #pragma unroll
        for (int off = 4; off; off >>= 1)
            sv += __shfl_xor_sync(0xFFFFFFFFu, sv, off);
        if (lane == 0) {
            atomicAdd(&g_acc, (double)sv);
            __threadfence();
            unsigned done = atomicAdd(&g_count, 1u);
            if (done == NUM_CTAS - 1) {
                double total = atomicAdd(&g_acc, 0.0);   // ordered read
                out[0] = (float)(total / ((double)N_DIM * (double)V_DIM));
                g_count = 0;   // reset for next graph replay
            }
        }
    }
}

// ============================================================
extern "C" void kernel_launch(void* const* d_in, const int* in_sizes, int n_in,
                              void* d_out, int out_size) {
    (void)in_sizes; (void)n_in; (void)out_size;
    const float* x = (const float*)d_in[0];   // [N, H]
    const float* y = (const float*)d_in[1];   // [N, V]
    const float* W = (const float*)d_in[2];   // [V, H]
    float* out = (float*)d_out;

    static bool attr_set = false;
    if (!attr_set) {
        cudaFuncSetAttribute(gemm_mse_kernel,
                             cudaFuncAttributeMaxDynamicSharedMemorySize,
                             SMEM_BYTES);
        attr_set = true;
    }

    convert_kernel<<<2048, 256>>>(x, W);

    dim3 grid(N_DIM / BM, V_DIM / BN);  // (16, 250): x-fastest -> W stripe L2 reuse
    gemm_mse_kernel<<<grid, THREADS, SMEM_BYTES>>>(y, out);
}

// round 14
// speedup vs baseline: 1.0838x; 1.0272x over previous
#include <cuda_runtime.h>
#include <cuda_fp16.h>
#include <cstdint>

#define N_DIM 2048
#define H_DIM 2048
#define V_DIM 32000

// ---- scratch ----
__device__ __half g_Wh[(size_t)V_DIM * H_DIM];   // 131 MB
__device__ __half g_xh[(size_t)N_DIM * H_DIM];   // 8 MB
__device__ double g_acc;
__device__ unsigned g_count = 0;

// ============================================================
// Kernel 1: fp32 -> fp16 conversion; zero accumulator
// ============================================================
__global__ void convert_kernel(const float* __restrict__ x,
                               const float* __restrict__ W) {
    size_t tid = (size_t)blockIdx.x * blockDim.x + threadIdx.x;
    size_t stride = (size_t)gridDim.x * blockDim.x;
    if (tid == 0) g_acc = 0.0;

    const size_t nW4 = (size_t)V_DIM * H_DIM / 4;
    const float4* W4 = (const float4*)W;
    for (size_t i = tid; i < nW4; i += stride) {
        float4 v = W4[i];
        __half2* dst = (__half2*)(g_Wh + i * 4);
        dst[0] = __floats2half2_rn(v.x, v.y);
        dst[1] = __floats2half2_rn(v.z, v.w);
    }
    const size_t nx4 = (size_t)N_DIM * H_DIM / 4;
    const float4* x4 = (const float4*)x;
    for (size_t i = tid; i < nx4; i += stride) {
        float4 v = x4[i];
        __half2* dst = (__half2*)(g_xh + i * 4);
        dst[0] = __floats2half2_rn(v.x, v.y);
        dst[1] = __floats2half2_rn(v.z, v.w);
    }
}

// ============================================================
// Kernel 2: fp16 HMMA GEMM (f16 acc), 2 CTAs/SM, fat warp tiles
//   CTA tile 128x256, BK=64; 8 warps (2 M x 4 N), warp tile 64x64
//   -> 8 ldmatrix per 32 MMAs (0.25 ldm/MMA, crossbar off critical path)
//   2-stage cp.async (96KB); fused MSE reduce + last-CTA finalize
// ============================================================
#define BM 128
#define BN 256
#define BK 64
#define NK (H_DIM / BK)               // 32
#define A_BYTES (BM * BK * 2)         // 16384
#define B_BYTES (BN * BK * 2)         // 32768
#define STAGE_BYTES (A_BYTES + B_BYTES)    // 49152
#define SMEM_BYTES (2 * STAGE_BYTES)       // 98304 -> 2 CTAs = 192KB
#define THREADS 256
#define NUM_CTAS ((N_DIM / BM) * (V_DIM / BN))   // 2000

__device__ __forceinline__ void cp_async16(uint32_t smem_addr, const void* gptr) {
    asm volatile("cp.async.cg.shared.global [%0], [%1], 16;"
                 :: "r"(smem_addr), "l"(gptr));
}

__global__ void __launch_bounds__(THREADS, 2)
gemm_mse_kernel(const float* __restrict__ y, float* __restrict__ out) {
    extern __shared__ __align__(1024) char smem[];
    __shared__ float red[8];

    const int tid = threadIdx.x;
    const int lane = tid & 31;
    const int warp = tid >> 5;
    const int warp_m = warp & 1;   // 0..1 -> 64-row slabs (M)
    const int warp_n = warp >> 1;  // 0..3 -> 64-col slabs (N)

    const uint32_t sbase = (uint32_t)__cvta_generic_to_shared(smem);

    const int n_blk = blockIdx.x * BM;
    const int v_blk = blockIdx.y * BN;
    const __half* gA = g_xh + (size_t)n_blk * H_DIM;
    const __half* gB = g_Wh + (size_t)v_blk * H_DIM;

    // loader: A 1024 chunks (4/thread), B 2048 chunks (8/thread)
    auto issue_tile = [&](int kt) {
        const uint32_t st = sbase + (kt & 1) * STAGE_BYTES;
        const __half* gAk = gA + kt * BK;
        const __half* gBk = gB + kt * BK;
        #pragma unroll
        for (int i = 0; i < 4; i++) {
            int chunk = i * THREADS + tid;   // 0..1023
            int row = chunk >> 3;            // 0..127
            int c16 = chunk & 7;
            uint32_t off = (uint32_t)(row * 128 + ((c16 ^ (row & 7)) * 16));
            cp_async16(st + off, gAk + (size_t)row * H_DIM + c16 * 8);
        }
        #pragma unroll
        for (int i = 0; i < 8; i++) {
            int chunk = i * THREADS + tid;   // 0..2047
            int row = chunk >> 3;            // 0..255
            int c16 = chunk & 7;
            uint32_t off = (uint32_t)(row * 128 + ((c16 ^ (row & 7)) * 16));
            cp_async16(st + A_BYTES + off, gBk + (size_t)row * H_DIM + c16 * 8);
        }
        asm volatile("cp.async.commit_group;");
    };

    issue_tile(0);

    // f16x2 accumulators: warp tile 64x64 -> 4 mi x 8 ni x 2 regs = 64 regs
    uint32_t c[4][8][2];
    #pragma unroll
    for (int mi = 0; mi < 4; mi++)
        #pragma unroll
        for (int ni = 0; ni < 8; ni++) { c[mi][ni][0] = 0u; c[mi][ni][1] = 0u; }

    // fragment addressing (round 5/6-validated 64x64 layout)
    const int a_row_base = warp_m * 64 + (lane & 15);
    const int a_kc_lane = lane >> 4;                  // 0/1
    const int b_row_base = warp_n * 64 + (lane & 7) + ((lane >> 4) << 3);
    const int b_kc_lane = (lane >> 3) & 1;

    for (int kt = 0; kt < NK; kt++) {
        asm volatile("cp.async.wait_group 0;");
        __syncthreads();
        if (kt + 1 < NK) issue_tile(kt + 1);   // overlaps compute of kt

        const uint32_t aBase = sbase + (kt & 1) * STAGE_BYTES;
        const uint32_t bBase = aBase + A_BYTES;

        #pragma unroll
        for (int ks = 0; ks < 4; ks++) {   // 4 x k16 per tile
            uint32_t a[4][4];
            #pragma unroll
            for (int mi = 0; mi < 4; mi++) {
                int row = a_row_base + mi * 16;
                int kc = ks * 2 + a_kc_lane;
                uint32_t addr = aBase + (uint32_t)(row * 128 + ((kc ^ (row & 7)) * 16));
                asm volatile(
                    "ldmatrix.sync.aligned.m8n8.x4.shared.b16 {%0,%1,%2,%3}, [%4];"
                    : "=r"(a[mi][0]), "=r"(a[mi][1]), "=r"(a[mi][2]), "=r"(a[mi][3])
                    : "r"(addr));
            }
            uint32_t b[4][4];
            #pragma unroll
            for (int p = 0; p < 4; p++) {
                int row = b_row_base + p * 16;
                int kc = ks * 2 + b_kc_lane;
                uint32_t addr = bBase + (uint32_t)(row * 128 + ((kc ^ (row & 7)) * 16));
                asm volatile(
                    "ldmatrix.sync.aligned.m8n8.x4.shared.b16 {%0,%1,%2,%3}, [%4];"
                    : "=r"(b[p][0]), "=r"(b[p][1]), "=r"(b[p][2]), "=r"(b[p][3])
                    : "r"(addr));
            }
            #pragma unroll
            for (int mi = 0; mi < 4; mi++) {
                #pragma unroll
                for (int ni = 0; ni < 8; ni++) {
                    int p = ni >> 1;
                    int o = (ni & 1) * 2;
                    asm volatile(
                        "mma.sync.aligned.m16n8k16.row.col.f16.f16.f16.f16 "
                        "{%0,%1}, {%2,%3,%4,%5}, {%6,%7}, {%0,%1};"
                        : "+r"(c[mi][ni][0]), "+r"(c[mi][ni][1])
                        : "r"(a[mi][0]), "r"(a[mi][1]), "r"(a[mi][2]), "r"(a[mi][3]),
                          "r"(b[p][o]), "r"(b[p][o + 1]));
                }
            }
        }
    }

    // ---- epilogue: (logit - y)^2 ----
    const int gr = lane >> 2;
    const int gc = (lane & 3) * 2;
    float acc = 0.0f;
    #pragma unroll
    for (int mi = 0; mi < 4; mi++) {
        int gn0 = n_blk + warp_m * 64 + mi * 16 + gr;
        const float* y0 = y + (size_t)gn0 * V_DIM + v_blk;
        const float* y8 = y0 + (size_t)8 * V_DIM;
        #pragma unroll
        for (int ni = 0; ni < 8; ni++) {
            int col = warp_n * 64 + ni * 8 + gc;
            float2 y01 = *(const float2*)(y0 + col);
            float2 y23 = *(const float2*)(y8 + col);
            float2 c01 = __half22float2(*(__half2*)&c[mi][ni][0]);
            float2 c23 = __half22float2(*(__half2*)&c[mi][ni][1]);
            float d0 = c01.x - y01.x;
            float d1 = c01.y - y01.y;
            float d2 = c23.x - y23.x;
            float d3 = c23.y - y23.y;
            acc += d0 * d0 + d1 * d1 + d2 * d2 + d3 * d3;
        }
    }
    #pragma unroll
    for (int off = 16; off; off >>= 1)
        acc += __shfl_xor_sync(0xFFFFFFFFu, acc, off);
    if (lane == 0) red[warp] = acc;
    __syncthreads();
    if (warp == 0) {
        float sv = (lane < 8) ? red[lane] : 0.0f;
        #pragma unroll
        for (int off = 4; off; off >>= 1)
            sv += __shfl_xor_sync(0xFFFFFFFFu, sv, off);
        if (lane == 0) {
            atomicAdd(&g_acc, (double)sv);
            __threadfence();
            unsigned done = atomicAdd(&g_count, 1u);
            if (done == NUM_CTAS - 1) {
                double total = atomicAdd(&g_acc, 0.0);   // ordered read
                out[0] = (float)(total / ((double)N_DIM * (double)V_DIM));
                g_count = 0;   // reset for next graph replay
            }
        }
    }
}

// ============================================================
extern "C" void kernel_launch(void* const* d_in, const int* in_sizes, int n_in,
                              void* d_out, int out_size) {
    (void)in_sizes; (void)n_in; (void)out_size;
    const float* x = (const float*)d_in[0];   // [N, H]
    const float* y = (const float*)d_in[1];   // [N, V]
    const float* W = (const float*)d_in[2];   // [V, H]
    float* out = (float*)d_out;

    static bool attr_set = false;
    if (!attr_set) {
        cudaFuncSetAttribute(gemm_mse_kernel,
                             cudaFuncAttributeMaxDynamicSharedMemorySize,
                             SMEM_BYTES);
        attr_set = true;
    }

    convert_kernel<<<2048, 256>>>(x, W);

    dim3 grid(N_DIM / BM, V_DIM / BN);  // (16, 125): x-fastest -> W stripe L2 reuse
    gemm_mse_kernel<<<grid, THREADS, SMEM_BYTES>>>(y, out);
}